// round 10
// baseline (speedup 1.0000x reference)
#include <cuda_runtime.h>
#include <cooperative_groups.h>
#include <cstdint>
#include <cstddef>

namespace cg = cooperative_groups;

#define N_JOBS 100000
#define N_MACH 10000
#define DIM 128
#define KDIM 256
#define BM 64
#define LN_EPS 1e-5f
#define MAX_EDGES 1600000

#define JOB_TILES ((N_JOBS + BM - 1) / BM)    // 1563
#define MACH_TILES ((N_MACH + BM - 1) / BM)   // 157

#define SCAN_CHUNK 512
#define JB ((N_JOBS + SCAN_CHUNK - 1) / SCAN_CHUNK)   // 196
#define MB ((N_MACH + SCAN_CHUNK - 1) / SCAN_CHUNK)   // 20

// Scratch device globals (no allocations allowed): CSR ~14MB + agg ~56MB.
__device__ int g_job_off[N_JOBS + 1];
__device__ int g_mach_off[N_MACH + 1];
__device__ int g_job_cur[N_JOBS];
__device__ int g_mach_cur[N_MACH];
__device__ int g_job_nbr[MAX_EDGES];
__device__ int g_mach_nbr[MAX_EDGES];
__device__ int g_bsum[JB + MB];
__device__ __align__(256) float g_job_agg[(size_t)N_JOBS * DIM];
__device__ __align__(256) float g_mach_agg[(size_t)N_MACH * DIM];

__global__ void zero_cnt_kernel() {
    int i = blockIdx.x * blockDim.x + threadIdx.x;
    int stride = gridDim.x * blockDim.x;
    for (int t = i; t < N_JOBS; t += stride) g_job_cur[t] = 0;
    for (int t = i; t < N_MACH; t += stride) g_mach_cur[t] = 0;
}

// One cooperative kernel: hist -> scanA -> scanB -> scanC -> fill, separated
// by grid.sync(). Phases are grid-stride so any co-resident grid size works.
__global__ void __launch_bounds__(256, 4) coop_build_kernel(
    const int* __restrict__ job_idx, const int* __restrict__ mach_idx, int n_edges)
{
    cg::grid_group grid = cg::this_grid();
    int tid = threadIdx.x;
    int gid = blockIdx.x * blockDim.x + tid;
    int gstride = gridDim.x * blockDim.x;
    int lane = tid & 31, wid = tid >> 5;
    __shared__ int wsum[8];

    // ---- phase 1: histogram (4 edges/iter -> 8 atomics in flight) ----
    {
        int n4 = n_edges >> 2;
        const int4* j4 = (const int4*)job_idx;
        const int4* m4 = (const int4*)mach_idx;
        for (int e = gid; e < n4; e += gstride) {
            int4 a = __ldg(j4 + e);
            int4 b = __ldg(m4 + e);
            atomicAdd(&g_job_cur[a.x], 1);  atomicAdd(&g_job_cur[a.y], 1);
            atomicAdd(&g_job_cur[a.z], 1);  atomicAdd(&g_job_cur[a.w], 1);
            atomicAdd(&g_mach_cur[b.x], 1); atomicAdd(&g_mach_cur[b.y], 1);
            atomicAdd(&g_mach_cur[b.z], 1); atomicAdd(&g_mach_cur[b.w], 1);
        }
        int rem = n_edges & 3;
        if (gid < rem) {
            int e = (n4 << 2) + gid;
            atomicAdd(&g_job_cur[__ldg(job_idx + e)], 1);
            atomicAdd(&g_mach_cur[__ldg(mach_idx + e)], 1);
        }
    }
    grid.sync();

    // ---- phase 2: scanA — per-chunk local exclusive scan, total -> g_bsum ----
    for (int blk = blockIdx.x; blk < JB + MB; blk += gridDim.x) {
        bool is_mach = blk >= JB;
        const int* cnt = is_mach ? g_mach_cur : g_job_cur;
        int* off = is_mach ? g_mach_off : g_job_off;
        int n    = is_mach ? N_MACH : N_JOBS;
        int b    = is_mach ? (blk - JB) : blk;

        int idx = b * SCAN_CHUNK + tid * 2;
        int v0 = (idx     < n) ? cnt[idx]     : 0;
        int v1 = (idx + 1 < n) ? cnt[idx + 1] : 0;
        int tsum = v0 + v1;
        int incl = tsum;
        #pragma unroll
        for (int o = 1; o < 32; o <<= 1) {
            int t = __shfl_up_sync(0xffffffffu, incl, o);
            if (lane >= o) incl += t;
        }
        if (lane == 31) wsum[wid] = incl;
        __syncthreads();
        if (tid < 8) {
            int ws = wsum[tid];
            #pragma unroll
            for (int o = 1; o < 8; o <<= 1) {
                int t = __shfl_up_sync(0xffu, ws, o);
                if (tid >= o) ws += t;
            }
            wsum[tid] = ws;
        }
        __syncthreads();
        int base = (wid == 0 ? 0 : wsum[wid - 1]) + (incl - tsum);
        if (idx     < n) off[idx]     = base;
        if (idx + 1 < n) off[idx + 1] = base + v0;
        if (tid == 255) g_bsum[blk] = wsum[7];
        __syncthreads();
    }
    grid.sync();

    // ---- phase 3: scanB — block 0 scans g_bsum segments ----
    if (blockIdx.x == 0) {
        #pragma unroll
        for (int seg = 0; seg < 2; seg++) {
            int n = seg ? MB : JB;
            int o0 = seg ? JB : 0;
            int v = (tid < n) ? g_bsum[o0 + tid] : 0;
            int incl = v;
            #pragma unroll
            for (int o = 1; o < 32; o <<= 1) {
                int t = __shfl_up_sync(0xffffffffu, incl, o);
                if (lane >= o) incl += t;
            }
            if (lane == 31) wsum[wid] = incl;
            __syncthreads();
            if (tid < 8) {
                int ws = wsum[tid];
                #pragma unroll
                for (int o = 1; o < 8; o <<= 1) {
                    int t = __shfl_up_sync(0xffu, ws, o);
                    if (tid >= o) ws += t;
                }
                wsum[tid] = ws;
            }
            __syncthreads();
            int excl = (wid == 0 ? 0 : wsum[wid - 1]) + (incl - v);
            if (tid < n) g_bsum[o0 + tid] = excl;
            __syncthreads();
        }
        if (tid == 0) { g_job_off[N_JOBS] = n_edges; g_mach_off[N_MACH] = n_edges; }
    }
    grid.sync();

    // ---- phase 4: scanC — add block bases, set cursors ----
    for (int blk = blockIdx.x; blk < JB + MB; blk += gridDim.x) {
        bool is_mach = blk >= JB;
        int* off = is_mach ? g_mach_off : g_job_off;
        int* cur = is_mach ? g_mach_cur : g_job_cur;
        int n    = is_mach ? N_MACH : N_JOBS;
        int b    = is_mach ? (blk - JB) : blk;
        int base = g_bsum[blk];
        int idx = b * SCAN_CHUNK + tid * 2;
        if (idx < n)     { int v = off[idx]     + base; off[idx]     = v; cur[idx]     = v; }
        if (idx + 1 < n) { int v = off[idx + 1] + base; off[idx + 1] = v; cur[idx + 1] = v; }
    }
    grid.sync();

    // ---- phase 5: fill (4 edges/iter -> 8 independent atomic+store chains) ----
    {
        int n4 = n_edges >> 2;
        const int4* j4 = (const int4*)job_idx;
        const int4* m4 = (const int4*)mach_idx;
        for (int e = gid; e < n4; e += gstride) {
            int4 a = __ldg(j4 + e);
            int4 b = __ldg(m4 + e);
            int p0 = atomicAdd(&g_job_cur[a.x], 1);
            int p1 = atomicAdd(&g_job_cur[a.y], 1);
            int p2 = atomicAdd(&g_job_cur[a.z], 1);
            int p3 = atomicAdd(&g_job_cur[a.w], 1);
            int q0 = atomicAdd(&g_mach_cur[b.x], 1);
            int q1 = atomicAdd(&g_mach_cur[b.y], 1);
            int q2 = atomicAdd(&g_mach_cur[b.z], 1);
            int q3 = atomicAdd(&g_mach_cur[b.w], 1);
            g_job_nbr[p0] = b.x;  g_job_nbr[p1] = b.y;
            g_job_nbr[p2] = b.z;  g_job_nbr[p3] = b.w;
            g_mach_nbr[q0] = a.x; g_mach_nbr[q1] = a.y;
            g_mach_nbr[q2] = a.z; g_mach_nbr[q3] = a.w;
        }
        int rem = n_edges & 3;
        if (gid < rem) {
            int e = (n4 << 2) + gid;
            int j = __ldg(job_idx + e);
            int m = __ldg(mach_idx + e);
            g_job_nbr[atomicAdd(&g_job_cur[j], 1)] = m;
            g_mach_nbr[atomicAdd(&g_mach_cur[m], 1)] = j;
        }
    }
}

// Warp per row: CSR gather-mean (fp32). Lane owns 4 floats.
// Unroll-4 -> 4 independent 512B gathers in flight per warp.
__global__ __launch_bounds__(256) void agg_kernel(const float* __restrict__ job_h,
                                                  const float* __restrict__ machine_h) {
    int gw = (blockIdx.x * blockDim.x + threadIdx.x) >> 5;
    if (gw >= N_JOBS + N_MACH) return;
    int lane = threadIdx.x & 31;
    const int* off; const int* nbr; const float* src; float* dst; int r;
    if (gw < N_JOBS) { r = gw;          off = g_job_off;  nbr = g_job_nbr;  src = machine_h; dst = g_job_agg; }
    else             { r = gw - N_JOBS; off = g_mach_off; nbr = g_mach_nbr; src = job_h;     dst = g_mach_agg; }
    int s = off[r], e = off[r + 1];
    int c = lane << 2;
    float4 a0 = make_float4(0.f, 0.f, 0.f, 0.f);
    float4 a1 = a0, a2 = a0, a3 = a0;
    int p = s;
    for (; p + 4 <= e; p += 4) {
        int n0 = __ldg(nbr + p);
        int n1 = __ldg(nbr + p + 1);
        int n2 = __ldg(nbr + p + 2);
        int n3 = __ldg(nbr + p + 3);
        float4 v0 = *(const float4*)(src + (size_t)n0 * DIM + c);
        float4 v1 = *(const float4*)(src + (size_t)n1 * DIM + c);
        float4 v2 = *(const float4*)(src + (size_t)n2 * DIM + c);
        float4 v3 = *(const float4*)(src + (size_t)n3 * DIM + c);
        a0.x += v0.x; a0.y += v0.y; a0.z += v0.z; a0.w += v0.w;
        a1.x += v1.x; a1.y += v1.y; a1.z += v1.z; a1.w += v1.w;
        a2.x += v2.x; a2.y += v2.y; a2.z += v2.z; a2.w += v2.w;
        a3.x += v3.x; a3.y += v3.y; a3.z += v3.z; a3.w += v3.w;
    }
    for (; p < e; p++) {
        int n0 = __ldg(nbr + p);
        float4 v0 = *(const float4*)(src + (size_t)n0 * DIM + c);
        a0.x += v0.x; a0.y += v0.y; a0.z += v0.z; a0.w += v0.w;
    }
    float idg = 1.0f / (float)max(e - s, 1);
    a0.x = (a0.x + a1.x + a2.x + a3.x) * idg;
    a0.y = (a0.y + a1.y + a2.y + a3.y) * idg;
    a0.z = (a0.z + a1.z + a2.z + a3.z) * idg;
    a0.w = (a0.w + a1.w + a2.w + a3.w) * idg;
    *(float4*)(dst + (size_t)r * DIM + c) = a0;
}

// ---- merged persistent GEMM+ReLU+LN, software-pipelined inner loop ---------
__device__ __forceinline__ void load_W_smem(float* Wt, const float* __restrict__ W, int tid) {
    #pragma unroll 4
    for (int it = 0; it < 32; it++) {
        int idx4 = tid + it * 256;          // 8192 float4 of W
        int o  = idx4 & 127;
        int k4 = (idx4 >> 7) << 2;
        float4 w = *(const float4*)(W + o * KDIM + k4);
        Wt[(k4 + 0) * DIM + o] = w.x;
        Wt[(k4 + 1) * DIM + o] = w.y;
        Wt[(k4 + 2) * DIM + o] = w.z;
        Wt[(k4 + 3) * DIM + o] = w.w;
    }
}

__device__ __forceinline__ void do_tile(
    int tile, const float* __restrict__ h, const float* __restrict__ agg,
    float4 bb, float4 gs, float4 gb,
    float* __restrict__ out, int n_rows,
    const float* Wt, float* Xs, int tid)
{
    int row0 = tile * BM;
    #pragma unroll 4
    for (int it = 0; it < 16; it++) {
        int idx4 = tid + it * 256;
        int r  = idx4 >> 6;
        int c4 = (idx4 & 63) << 2;
        int grow = min(row0 + r, n_rows - 1);
        float4 v;
        if (c4 < DIM) v = *(const float4*)(h + (size_t)grow * DIM + c4);
        else          v = *(const float4*)(agg + (size_t)grow * DIM + (c4 - DIM));
        *(float4*)(Xs + r * KDIM + c4) = v;
    }
    __syncthreads();

    int tc = tid & 31;
    int w  = tid >> 5;
    unsigned long long acc[8][2];
    #pragma unroll
    for (int i = 0; i < 8; i++) { acc[i][0] = 0ull; acc[i][1] = 0ull; }
    const float* xbase = Xs + (size_t)(w * 8) * KDIM;

    // Software-pipelined: prefetch next chunk's W fragments + X broadcasts into
    // regs while this chunk's 64 FMAs issue — hides the 29-cyc LDS latency.
    ulonglong2 bq[4];
    float4 xa[8];
    {
        const float* wp = Wt + tc * 4;
        #pragma unroll
        for (int kk = 0; kk < 4; kk++) bq[kk] = *(const ulonglong2*)(wp + kk * DIM);
        #pragma unroll
        for (int i = 0; i < 8; i++) xa[i] = *(const float4*)(xbase + i * KDIM);
    }

    #pragma unroll 2
    for (int k0 = 0; k0 < KDIM; k0 += 4) {
        ulonglong2 bqn[4];
        float4 xan[8];
        if (k0 + 4 < KDIM) {
            const float* wp = Wt + (size_t)(k0 + 4) * DIM + tc * 4;
            #pragma unroll
            for (int kk = 0; kk < 4; kk++) bqn[kk] = *(const ulonglong2*)(wp + kk * DIM);
            #pragma unroll
            for (int i = 0; i < 8; i++) xan[i] = *(const float4*)(xbase + i * KDIM + k0 + 4);
        }
        #pragma unroll
        for (int i = 0; i < 8; i++) {
            float av[4] = {xa[i].x, xa[i].y, xa[i].z, xa[i].w};
            #pragma unroll
            for (int kk = 0; kk < 4; kk++) {
                unsigned long long aa;
                asm("mov.b64 %0, {%1, %1};" : "=l"(aa) : "f"(av[kk]));
                asm("fma.rn.f32x2 %0, %1, %2, %0;" : "+l"(acc[i][0]) : "l"(aa), "l"(bq[kk].x));
                asm("fma.rn.f32x2 %0, %1, %2, %0;" : "+l"(acc[i][1]) : "l"(aa), "l"(bq[kk].y));
            }
        }
        if (k0 + 4 < KDIM) {
            #pragma unroll
            for (int kk = 0; kk < 4; kk++) bq[kk] = bqn[kk];
            #pragma unroll
            for (int i = 0; i < 8; i++) xa[i] = xan[i];
        }
    }

    #pragma unroll
    for (int i = 0; i < 8; i++) {
        int grow = row0 + w * 8 + i;
        float v0, v1, v2, v3;
        asm("mov.b64 {%0, %1}, %2;" : "=f"(v0), "=f"(v1) : "l"(acc[i][0]));
        asm("mov.b64 {%0, %1}, %2;" : "=f"(v2), "=f"(v3) : "l"(acc[i][1]));
        v0 = fmaxf(v0 + bb.x, 0.f);
        v1 = fmaxf(v1 + bb.y, 0.f);
        v2 = fmaxf(v2 + bb.z, 0.f);
        v3 = fmaxf(v3 + bb.w, 0.f);
        float sum = v0 + v1 + v2 + v3;
        float sq  = v0*v0 + v1*v1 + v2*v2 + v3*v3;
        #pragma unroll
        for (int o = 16; o > 0; o >>= 1) {
            sum += __shfl_xor_sync(0xffffffffu, sum, o);
            sq  += __shfl_xor_sync(0xffffffffu, sq,  o);
        }
        float mean = sum * (1.0f / 128.0f);
        float var  = sq * (1.0f / 128.0f) - mean * mean;
        float rstd = rsqrtf(var + LN_EPS);
        if (grow < n_rows) {
            float4 o4;
            o4.x = (v0 - mean) * rstd * gs.x + gb.x;
            o4.y = (v1 - mean) * rstd * gs.y + gb.y;
            o4.z = (v2 - mean) * rstd * gs.z + gb.z;
            o4.w = (v3 - mean) * rstd * gs.w + gb.w;
            *(float4*)(out + (size_t)grow * DIM + tc * 4) = o4;
        }
    }
    __syncthreads();
}

__global__ __launch_bounds__(256, 1) void gemm_ln_kernel(
    const float* __restrict__ job_h, const float* __restrict__ machine_h,
    const float* __restrict__ Wj, const float* __restrict__ bj,
    const float* __restrict__ lnsj, const float* __restrict__ lnbj,
    const float* __restrict__ Wm, const float* __restrict__ bm,
    const float* __restrict__ lnsm, const float* __restrict__ lnbm,
    float* __restrict__ out)
{
    extern __shared__ float smem[];
    float* Wt = smem;                 // 256*128
    float* Xs = smem + KDIM * DIM;    // 64*256
    int tid = threadIdx.x;
    int tc = tid & 31;

    load_W_smem(Wt, Wj, tid);
    __syncthreads();
    {
        float4 bb = *(const float4*)(bj + tc * 4);
        float4 gs = *(const float4*)(lnsj + tc * 4);
        float4 gb = *(const float4*)(lnbj + tc * 4);
        int t = blockIdx.x;
        for (; t < JOB_TILES; t += gridDim.x)
            do_tile(t, job_h, g_job_agg, bb, gs, gb, out, N_JOBS, Wt, Xs, tid);
    }

    __syncthreads();
    load_W_smem(Wt, Wm, tid);
    __syncthreads();
    {
        float4 bb = *(const float4*)(bm + tc * 4);
        float4 gs = *(const float4*)(lnsm + tc * 4);
        float4 gb = *(const float4*)(lnbm + tc * 4);
        int t = blockIdx.x;
        while (t < JOB_TILES) t += gridDim.x;
        for (; t < JOB_TILES + MACH_TILES; t += gridDim.x)
            do_tile(t - JOB_TILES, machine_h, g_mach_agg, bb, gs, gb,
                    out + (size_t)N_JOBS * DIM, N_MACH, Wt, Xs, tid);
    }
}

extern "C" void kernel_launch(void* const* d_in, const int* in_sizes, int n_in,
                              void* d_out, int out_size)
{
    const float* job_h     = (const float*)d_in[0];
    const float* machine_h = (const float*)d_in[1];
    const float* W_job_w   = (const float*)d_in[2];
    const float* W_job_b   = (const float*)d_in[3];
    const float* W_mach_w  = (const float*)d_in[4];
    const float* W_mach_b  = (const float*)d_in[5];
    const float* lnj_s     = (const float*)d_in[6];
    const float* lnj_b     = (const float*)d_in[7];
    const float* lnm_s     = (const float*)d_in[8];
    const float* lnm_b     = (const float*)d_in[9];
    const int*   job_idx   = (const int*)d_in[10];
    const int*   mach_idx  = (const int*)d_in[11];
    float* out = (float*)d_out;
    int n_edges = in_sizes[10];

    const int smem_bytes = (KDIM * DIM + BM * KDIM) * (int)sizeof(float);  // 196608
    cudaFuncSetAttribute(gemm_ln_kernel, cudaFuncAttributeMaxDynamicSharedMemorySize, smem_bytes);

    // Launch 1: zero cursors
    zero_cnt_kernel<<<128, 256>>>();

    // Launch 2: cooperative CSR build (hist -> scans -> fill with grid.sync)
    {
        int max_blocks_per_sm = 0;
        cudaOccupancyMaxActiveBlocksPerMultiprocessor(
            &max_blocks_per_sm, coop_build_kernel, 256, 0);
        if (max_blocks_per_sm < 1) max_blocks_per_sm = 1;
        int dev = 0, n_sm = 148;
        cudaGetDevice(&dev);
        cudaDeviceGetAttribute(&n_sm, cudaDevAttrMultiProcessorCount, dev);
        int grid = n_sm * max_blocks_per_sm;
        if (grid > 592) grid = 592;
        void* cargs[] = { (void*)&job_idx, (void*)&mach_idx, (void*)&n_edges };
        cudaLaunchCooperativeKernel((const void*)coop_build_kernel,
                                    dim3(grid, 1, 1), dim3(256, 1, 1),
                                    cargs, 0, (cudaStream_t)0);
    }

    // Launch 3: CSR gather-mean (fp32)
    agg_kernel<<<(int)(((size_t)(N_JOBS + N_MACH) * 32 + 255) / 256), 256>>>(job_h, machine_h);

    // Launch 4: persistent fused GEMM+ReLU+LN  (ncu captures launch #4)
    gemm_ln_kernel<<<148, 256, smem_bytes>>>(
        job_h, machine_h,
        W_job_w, W_job_b, lnj_s, lnj_b,
        W_mach_w, W_mach_b, lnm_s, lnm_b,
        out);
}

// round 11
// speedup vs baseline: 1.1687x; 1.1687x over previous
#include <cuda_runtime.h>
#include <cooperative_groups.h>
#include <cstdint>
#include <cstddef>

namespace cg = cooperative_groups;

#define N_JOBS 100000
#define N_MACH 10000
#define DIM 128
#define KDIM 256
#define BM 96
#define THREADS_G 384
#define LN_EPS 1e-5f
#define MAX_EDGES 1600000

#define JOB_TILES ((N_JOBS + BM - 1) / BM)    // 1042
#define MACH_TILES ((N_MACH + BM - 1) / BM)   // 105

#define SCAN_CHUNK 512
#define JB ((N_JOBS + SCAN_CHUNK - 1) / SCAN_CHUNK)   // 196
#define MB ((N_MACH + SCAN_CHUNK - 1) / SCAN_CHUNK)   // 20

// Scratch device globals (no allocations allowed): CSR ~14MB + agg ~56MB.
__device__ int g_job_off[N_JOBS + 1];
__device__ int g_mach_off[N_MACH + 1];
__device__ int g_job_cur[N_JOBS];
__device__ int g_mach_cur[N_MACH];
__device__ int g_job_nbr[MAX_EDGES];
__device__ int g_mach_nbr[MAX_EDGES];
__device__ int g_bsum[JB + MB];
__device__ __align__(256) float g_job_agg[(size_t)N_JOBS * DIM];
__device__ __align__(256) float g_mach_agg[(size_t)N_MACH * DIM];

__global__ void zero_cnt_kernel() {
    int i = blockIdx.x * blockDim.x + threadIdx.x;
    int stride = gridDim.x * blockDim.x;
    for (int t = i; t < N_JOBS; t += stride) g_job_cur[t] = 0;
    for (int t = i; t < N_MACH; t += stride) g_mach_cur[t] = 0;
}

// One cooperative kernel: hist -> scanA -> scanB -> scanC -> fill, separated
// by grid.sync(). Phases are grid-stride so any co-resident grid size works.
__global__ void __launch_bounds__(256, 4) coop_build_kernel(
    const int* __restrict__ job_idx, const int* __restrict__ mach_idx, int n_edges)
{
    cg::grid_group grid = cg::this_grid();
    int tid = threadIdx.x;
    int gid = blockIdx.x * blockDim.x + tid;
    int gstride = gridDim.x * blockDim.x;
    int lane = tid & 31, wid = tid >> 5;
    __shared__ int wsum[8];

    // ---- phase 1: histogram (4 edges/iter -> 8 atomics in flight) ----
    {
        int n4 = n_edges >> 2;
        const int4* j4 = (const int4*)job_idx;
        const int4* m4 = (const int4*)mach_idx;
        for (int e = gid; e < n4; e += gstride) {
            int4 a = __ldg(j4 + e);
            int4 b = __ldg(m4 + e);
            atomicAdd(&g_job_cur[a.x], 1);  atomicAdd(&g_job_cur[a.y], 1);
            atomicAdd(&g_job_cur[a.z], 1);  atomicAdd(&g_job_cur[a.w], 1);
            atomicAdd(&g_mach_cur[b.x], 1); atomicAdd(&g_mach_cur[b.y], 1);
            atomicAdd(&g_mach_cur[b.z], 1); atomicAdd(&g_mach_cur[b.w], 1);
        }
        int rem = n_edges & 3;
        if (gid < rem) {
            int e = (n4 << 2) + gid;
            atomicAdd(&g_job_cur[__ldg(job_idx + e)], 1);
            atomicAdd(&g_mach_cur[__ldg(mach_idx + e)], 1);
        }
    }
    grid.sync();

    // ---- phase 2: scanA — per-chunk local exclusive scan, total -> g_bsum ----
    for (int blk = blockIdx.x; blk < JB + MB; blk += gridDim.x) {
        bool is_mach = blk >= JB;
        const int* cnt = is_mach ? g_mach_cur : g_job_cur;
        int* off = is_mach ? g_mach_off : g_job_off;
        int n    = is_mach ? N_MACH : N_JOBS;
        int b    = is_mach ? (blk - JB) : blk;

        int idx = b * SCAN_CHUNK + tid * 2;
        int v0 = (idx     < n) ? cnt[idx]     : 0;
        int v1 = (idx + 1 < n) ? cnt[idx + 1] : 0;
        int tsum = v0 + v1;
        int incl = tsum;
        #pragma unroll
        for (int o = 1; o < 32; o <<= 1) {
            int t = __shfl_up_sync(0xffffffffu, incl, o);
            if (lane >= o) incl += t;
        }
        if (lane == 31) wsum[wid] = incl;
        __syncthreads();
        if (tid < 8) {
            int ws = wsum[tid];
            #pragma unroll
            for (int o = 1; o < 8; o <<= 1) {
                int t = __shfl_up_sync(0xffu, ws, o);
                if (tid >= o) ws += t;
            }
            wsum[tid] = ws;
        }
        __syncthreads();
        int base = (wid == 0 ? 0 : wsum[wid - 1]) + (incl - tsum);
        if (idx     < n) off[idx]     = base;
        if (idx + 1 < n) off[idx + 1] = base + v0;
        if (tid == 255) g_bsum[blk] = wsum[7];
        __syncthreads();
    }
    grid.sync();

    // ---- phase 3: scanB — block 0 scans g_bsum segments ----
    if (blockIdx.x == 0) {
        #pragma unroll
        for (int seg = 0; seg < 2; seg++) {
            int n = seg ? MB : JB;
            int o0 = seg ? JB : 0;
            int v = (tid < n) ? g_bsum[o0 + tid] : 0;
            int incl = v;
            #pragma unroll
            for (int o = 1; o < 32; o <<= 1) {
                int t = __shfl_up_sync(0xffffffffu, incl, o);
                if (lane >= o) incl += t;
            }
            if (lane == 31) wsum[wid] = incl;
            __syncthreads();
            if (tid < 8) {
                int ws = wsum[tid];
                #pragma unroll
                for (int o = 1; o < 8; o <<= 1) {
                    int t = __shfl_up_sync(0xffu, ws, o);
                    if (tid >= o) ws += t;
                }
                wsum[tid] = ws;
            }
            __syncthreads();
            int excl = (wid == 0 ? 0 : wsum[wid - 1]) + (incl - v);
            if (tid < n) g_bsum[o0 + tid] = excl;
            __syncthreads();
        }
        if (tid == 0) { g_job_off[N_JOBS] = n_edges; g_mach_off[N_MACH] = n_edges; }
    }
    grid.sync();

    // ---- phase 4: scanC — add block bases, set cursors ----
    for (int blk = blockIdx.x; blk < JB + MB; blk += gridDim.x) {
        bool is_mach = blk >= JB;
        int* off = is_mach ? g_mach_off : g_job_off;
        int* cur = is_mach ? g_mach_cur : g_job_cur;
        int n    = is_mach ? N_MACH : N_JOBS;
        int b    = is_mach ? (blk - JB) : blk;
        int base = g_bsum[blk];
        int idx = b * SCAN_CHUNK + tid * 2;
        if (idx < n)     { int v = off[idx]     + base; off[idx]     = v; cur[idx]     = v; }
        if (idx + 1 < n) { int v = off[idx + 1] + base; off[idx + 1] = v; cur[idx + 1] = v; }
    }
    grid.sync();

    // ---- phase 5: fill (4 edges/iter -> 8 independent atomic+store chains) ----
    {
        int n4 = n_edges >> 2;
        const int4* j4 = (const int4*)job_idx;
        const int4* m4 = (const int4*)mach_idx;
        for (int e = gid; e < n4; e += gstride) {
            int4 a = __ldg(j4 + e);
            int4 b = __ldg(m4 + e);
            int p0 = atomicAdd(&g_job_cur[a.x], 1);
            int p1 = atomicAdd(&g_job_cur[a.y], 1);
            int p2 = atomicAdd(&g_job_cur[a.z], 1);
            int p3 = atomicAdd(&g_job_cur[a.w], 1);
            int q0 = atomicAdd(&g_mach_cur[b.x], 1);
            int q1 = atomicAdd(&g_mach_cur[b.y], 1);
            int q2 = atomicAdd(&g_mach_cur[b.z], 1);
            int q3 = atomicAdd(&g_mach_cur[b.w], 1);
            g_job_nbr[p0] = b.x;  g_job_nbr[p1] = b.y;
            g_job_nbr[p2] = b.z;  g_job_nbr[p3] = b.w;
            g_mach_nbr[q0] = a.x; g_mach_nbr[q1] = a.y;
            g_mach_nbr[q2] = a.z; g_mach_nbr[q3] = a.w;
        }
        int rem = n_edges & 3;
        if (gid < rem) {
            int e = (n4 << 2) + gid;
            int j = __ldg(job_idx + e);
            int m = __ldg(mach_idx + e);
            g_job_nbr[atomicAdd(&g_job_cur[j], 1)] = m;
            g_mach_nbr[atomicAdd(&g_mach_cur[m], 1)] = j;
        }
    }
}

// Warp per row: CSR gather-mean (fp32). Lane owns 4 floats.
// Unroll-4 -> 4 independent 512B gathers in flight per warp.
__global__ __launch_bounds__(256) void agg_kernel(const float* __restrict__ job_h,
                                                  const float* __restrict__ machine_h) {
    int gw = (blockIdx.x * blockDim.x + threadIdx.x) >> 5;
    if (gw >= N_JOBS + N_MACH) return;
    int lane = threadIdx.x & 31;
    const int* off; const int* nbr; const float* src; float* dst; int r;
    if (gw < N_JOBS) { r = gw;          off = g_job_off;  nbr = g_job_nbr;  src = machine_h; dst = g_job_agg; }
    else             { r = gw - N_JOBS; off = g_mach_off; nbr = g_mach_nbr; src = job_h;     dst = g_mach_agg; }
    int s = off[r], e = off[r + 1];
    int c = lane << 2;
    float4 a0 = make_float4(0.f, 0.f, 0.f, 0.f);
    float4 a1 = a0, a2 = a0, a3 = a0;
    int p = s;
    for (; p + 4 <= e; p += 4) {
        int n0 = __ldg(nbr + p);
        int n1 = __ldg(nbr + p + 1);
        int n2 = __ldg(nbr + p + 2);
        int n3 = __ldg(nbr + p + 3);
        float4 v0 = *(const float4*)(src + (size_t)n0 * DIM + c);
        float4 v1 = *(const float4*)(src + (size_t)n1 * DIM + c);
        float4 v2 = *(const float4*)(src + (size_t)n2 * DIM + c);
        float4 v3 = *(const float4*)(src + (size_t)n3 * DIM + c);
        a0.x += v0.x; a0.y += v0.y; a0.z += v0.z; a0.w += v0.w;
        a1.x += v1.x; a1.y += v1.y; a1.z += v1.z; a1.w += v1.w;
        a2.x += v2.x; a2.y += v2.y; a2.z += v2.z; a2.w += v2.w;
        a3.x += v3.x; a3.y += v3.y; a3.z += v3.z; a3.w += v3.w;
    }
    for (; p < e; p++) {
        int n0 = __ldg(nbr + p);
        float4 v0 = *(const float4*)(src + (size_t)n0 * DIM + c);
        a0.x += v0.x; a0.y += v0.y; a0.z += v0.z; a0.w += v0.w;
    }
    float idg = 1.0f / (float)max(e - s, 1);
    a0.x = (a0.x + a1.x + a2.x + a3.x) * idg;
    a0.y = (a0.y + a1.y + a2.y + a3.y) * idg;
    a0.z = (a0.z + a1.z + a2.z + a3.z) * idg;
    a0.w = (a0.w + a1.w + a2.w + a3.w) * idg;
    *(float4*)(dst + (size_t)r * DIM + c) = a0;
}

// ---- merged persistent GEMM+ReLU+LN: 384 threads, BM=96, 3 warps/SMSP ------
__device__ __forceinline__ void load_W_smem(float* Wt, const float* __restrict__ W, int tid) {
    // 8192 float4 of W over 384 threads: grid-stride
    for (int idx4 = tid; idx4 < 8192; idx4 += THREADS_G) {
        int o  = idx4 & 127;
        int k4 = (idx4 >> 7) << 2;
        float4 w = *(const float4*)(W + o * KDIM + k4);
        Wt[(k4 + 0) * DIM + o] = w.x;
        Wt[(k4 + 1) * DIM + o] = w.y;
        Wt[(k4 + 2) * DIM + o] = w.z;
        Wt[(k4 + 3) * DIM + o] = w.w;
    }
}

__device__ __forceinline__ void do_tile(
    int tile, const float* __restrict__ h, const float* __restrict__ agg,
    float4 bb, float4 gs, float4 gb,
    float* __restrict__ out, int n_rows,
    const float* Wt, float* Xs, int tid)
{
    int row0 = tile * BM;
    // Stage X tile: BM*KDIM/4 = 6144 float4, 16 per thread, coalesced.
    #pragma unroll 4
    for (int it = 0; it < 16; it++) {
        int idx4 = tid + it * THREADS_G;
        int r  = idx4 >> 6;
        int c4 = (idx4 & 63) << 2;
        int grow = min(row0 + r, n_rows - 1);
        float4 v;
        if (c4 < DIM) v = *(const float4*)(h + (size_t)grow * DIM + c4);
        else          v = *(const float4*)(agg + (size_t)grow * DIM + (c4 - DIM));
        *(float4*)(Xs + r * KDIM + c4) = v;
    }
    __syncthreads();

    int tc = tid & 31;
    int w  = tid >> 5;            // 0..11, owns rows w*8..w*8+7
    unsigned long long acc[8][2];
    #pragma unroll
    for (int i = 0; i < 8; i++) { acc[i][0] = 0ull; acc[i][1] = 0ull; }
    const float* xbase = Xs + (size_t)(w * 8) * KDIM;

    #pragma unroll 2
    for (int k0 = 0; k0 < KDIM; k0 += 4) {
        const float* wp = Wt + (size_t)k0 * DIM + tc * 4;
        ulonglong2 bq[4];
        #pragma unroll
        for (int kk = 0; kk < 4; kk++)
            bq[kk] = *(const ulonglong2*)(wp + kk * DIM);
        #pragma unroll
        for (int i = 0; i < 8; i++) {
            float4 a = *(const float4*)(xbase + i * KDIM + k0);
            float av[4] = {a.x, a.y, a.z, a.w};
            #pragma unroll
            for (int kk = 0; kk < 4; kk++) {
                unsigned long long aa;
                asm("mov.b64 %0, {%1, %1};" : "=l"(aa) : "f"(av[kk]));
                asm("fma.rn.f32x2 %0, %1, %2, %0;" : "+l"(acc[i][0]) : "l"(aa), "l"(bq[kk].x));
                asm("fma.rn.f32x2 %0, %1, %2, %0;" : "+l"(acc[i][1]) : "l"(aa), "l"(bq[kk].y));
            }
        }
    }

    #pragma unroll
    for (int i = 0; i < 8; i++) {
        int grow = row0 + w * 8 + i;
        float v0, v1, v2, v3;
        asm("mov.b64 {%0, %1}, %2;" : "=f"(v0), "=f"(v1) : "l"(acc[i][0]));
        asm("mov.b64 {%0, %1}, %2;" : "=f"(v2), "=f"(v3) : "l"(acc[i][1]));
        v0 = fmaxf(v0 + bb.x, 0.f);
        v1 = fmaxf(v1 + bb.y, 0.f);
        v2 = fmaxf(v2 + bb.z, 0.f);
        v3 = fmaxf(v3 + bb.w, 0.f);
        float sum = v0 + v1 + v2 + v3;
        float sq  = v0*v0 + v1*v1 + v2*v2 + v3*v3;
        #pragma unroll
        for (int o = 16; o > 0; o >>= 1) {
            sum += __shfl_xor_sync(0xffffffffu, sum, o);
            sq  += __shfl_xor_sync(0xffffffffu, sq,  o);
        }
        float mean = sum * (1.0f / 128.0f);
        float var  = sq * (1.0f / 128.0f) - mean * mean;
        float rstd = rsqrtf(var + LN_EPS);
        if (grow < n_rows) {
            float4 o4;
            o4.x = (v0 - mean) * rstd * gs.x + gb.x;
            o4.y = (v1 - mean) * rstd * gs.y + gb.y;
            o4.z = (v2 - mean) * rstd * gs.z + gb.z;
            o4.w = (v3 - mean) * rstd * gs.w + gb.w;
            *(float4*)(out + (size_t)grow * DIM + tc * 4) = o4;
        }
    }
    __syncthreads();
}

__global__ __launch_bounds__(THREADS_G, 1) void gemm_ln_kernel(
    const float* __restrict__ job_h, const float* __restrict__ machine_h,
    const float* __restrict__ Wj, const float* __restrict__ bj,
    const float* __restrict__ lnsj, const float* __restrict__ lnbj,
    const float* __restrict__ Wm, const float* __restrict__ bm,
    const float* __restrict__ lnsm, const float* __restrict__ lnbm,
    float* __restrict__ out)
{
    extern __shared__ float smem[];
    float* Wt = smem;                 // 256*128 = 128KB
    float* Xs = smem + KDIM * DIM;    // 96*256  = 96KB
    int tid = threadIdx.x;
    int tc = tid & 31;

    load_W_smem(Wt, Wj, tid);
    __syncthreads();
    {
        float4 bb = *(const float4*)(bj + tc * 4);
        float4 gs = *(const float4*)(lnsj + tc * 4);
        float4 gb = *(const float4*)(lnbj + tc * 4);
        int t = blockIdx.x;
        for (; t < JOB_TILES; t += gridDim.x)
            do_tile(t, job_h, g_job_agg, bb, gs, gb, out, N_JOBS, Wt, Xs, tid);
    }

    __syncthreads();
    load_W_smem(Wt, Wm, tid);
    __syncthreads();
    {
        float4 bb = *(const float4*)(bm + tc * 4);
        float4 gs = *(const float4*)(lnsm + tc * 4);
        float4 gb = *(const float4*)(lnbm + tc * 4);
        int t = blockIdx.x;
        while (t < JOB_TILES) t += gridDim.x;
        for (; t < JOB_TILES + MACH_TILES; t += gridDim.x)
            do_tile(t - JOB_TILES, machine_h, g_mach_agg, bb, gs, gb,
                    out + (size_t)N_JOBS * DIM, N_MACH, Wt, Xs, tid);
    }
}

extern "C" void kernel_launch(void* const* d_in, const int* in_sizes, int n_in,
                              void* d_out, int out_size)
{
    const float* job_h     = (const float*)d_in[0];
    const float* machine_h = (const float*)d_in[1];
    const float* W_job_w   = (const float*)d_in[2];
    const float* W_job_b   = (const float*)d_in[3];
    const float* W_mach_w  = (const float*)d_in[4];
    const float* W_mach_b  = (const float*)d_in[5];
    const float* lnj_s     = (const float*)d_in[6];
    const float* lnj_b     = (const float*)d_in[7];
    const float* lnm_s     = (const float*)d_in[8];
    const float* lnm_b     = (const float*)d_in[9];
    const int*   job_idx   = (const int*)d_in[10];
    const int*   mach_idx  = (const int*)d_in[11];
    float* out = (float*)d_out;
    int n_edges = in_sizes[10];

    const int smem_bytes = (KDIM * DIM + BM * KDIM) * (int)sizeof(float);  // 229376
    cudaFuncSetAttribute(gemm_ln_kernel, cudaFuncAttributeMaxDynamicSharedMemorySize, smem_bytes);

    // Launch 1: zero cursors
    zero_cnt_kernel<<<128, 256>>>();

    // Launch 2: cooperative CSR build (hist -> scans -> fill with grid.sync)
    {
        int max_blocks_per_sm = 0;
        cudaOccupancyMaxActiveBlocksPerMultiprocessor(
            &max_blocks_per_sm, coop_build_kernel, 256, 0);
        if (max_blocks_per_sm < 1) max_blocks_per_sm = 1;
        int dev = 0, n_sm = 148;
        cudaGetDevice(&dev);
        cudaDeviceGetAttribute(&n_sm, cudaDevAttrMultiProcessorCount, dev);
        int grid = n_sm * max_blocks_per_sm;
        if (grid > 592) grid = 592;
        void* cargs[] = { (void*)&job_idx, (void*)&mach_idx, (void*)&n_edges };
        cudaLaunchCooperativeKernel((const void*)coop_build_kernel,
                                    dim3(grid, 1, 1), dim3(256, 1, 1),
                                    cargs, 0, (cudaStream_t)0);
    }

    // Launch 3: CSR gather-mean (fp32)
    agg_kernel<<<(int)(((size_t)(N_JOBS + N_MACH) * 32 + 255) / 256), 256>>>(job_h, machine_h);

    // Launch 4: persistent fused GEMM+ReLU+LN  (ncu captures launch #4)
    gemm_ln_kernel<<<148, THREADS_G, smem_bytes>>>(
        job_h, machine_h,
        W_job_w, W_job_b, lnj_s, lnj_b,
        W_mach_w, W_mach_b, lnm_s, lnm_b,
        out);
}